// round 2
// baseline (speedup 1.0000x reference)
#include <cuda_runtime.h>

#define BB 4
#define NN 20000
#define EE 320000
#define IND 21
#define ED 64
#define H2 128
#define NL 3
#define BN_EPS 1e-5f

#define HSZ  (BB*NN*ED)   // 5,120,000 floats
#define H2SZ (BB*NN*H2)   // 10,240,000 floats

// ---- device scratch (allocation-free rule: __device__ globals) ----
__device__ float g_h0[HSZ];
__device__ float g_h1[HSZ];
__device__ float g_aggr[HSZ];
__device__ float g_h2[H2SZ];
__device__ int   g_src[BB*EE];
__device__ int   g_dst[BB*EE];
__device__ float g_s[BB*NN];
__device__ float g_deg[BB*NN];
__device__ float g_sum[BB*H2];
__device__ float g_sumsq[BB*H2];
__device__ float g_bnA[BB*H2];
__device__ float g_bnC[BB*H2];
__device__ float g_u[H2];
__device__ float g_v[H2];
__device__ int   g_is64;

// ---- dtype detection: int64 edge_index has all-zero high words ----
__global__ void k_detect(const unsigned int* __restrict__ ei32) {
    __shared__ unsigned int sOr[256];
    unsigned int v = ei32[2 * threadIdx.x + 1];
    sOr[threadIdx.x] = v;
    __syncthreads();
    for (int s = 128; s > 0; s >>= 1) {
        if (threadIdx.x < s) sOr[threadIdx.x] |= sOr[threadIdx.x + s];
        __syncthreads();
    }
    if (threadIdx.x == 0) g_is64 = (sOr[0] == 0) ? 1 : 0;
}

// ---- decode indices to int32 + layer-invariant s/deg sums ----
__global__ void k_prep(const void* __restrict__ ei, const float* __restrict__ ea) {
    int idx = blockIdx.x * 256 + threadIdx.x;
    if (idx >= BB * EE) return;
    int b = idx / EE;
    int e = idx - b * EE;
    int src, dst;
    if (g_is64) {
        const long long* p = (const long long*)ei + (long long)b * 2 * EE;
        src = (int)p[e];
        dst = (int)p[EE + e];
    } else {
        const int* p = (const int*)ei + (long long)b * 2 * EE;
        src = p[e];
        dst = p[EE + e];
    }
    g_src[idx] = src;
    g_dst[idx] = dst;
    atomicAdd(&g_s[b * NN + dst], ea[idx]);
    atomicAdd(&g_deg[b * NN + dst], 1.0f);
}

// ---- input embedding: h0 = x @ inW + inb ----
__global__ void __launch_bounds__(256) k_embed(const float* __restrict__ x,
                                               const float* __restrict__ inW,
                                               const float* __restrict__ inb) {
    __shared__ float sX[4 * 22];
    __shared__ float sWn[IND * ED];
    int tid = threadIdx.x;
    int nid0 = blockIdx.x * 4;
    for (int i = tid; i < IND * ED; i += 256) sWn[i] = inW[i];
    if (tid < 4 * IND) {
        int loc = tid / IND, ii = tid - loc * IND;
        sX[loc * 22 + ii] = x[(long long)(nid0 + loc) * IND + ii];
    }
    __syncthreads();
    int j = tid & 63, loc = tid >> 6;
    float acc = inb[j];
#pragma unroll
    for (int i = 0; i < IND; i++) acc += sX[loc * 22 + i] * sWn[i * ED + j];
    g_h0[(long long)(nid0 + loc) * ED + j] = acc;
}

// ---- per-layer rank-2 fold: u = edgeW @ W1[64:128,:], v = edgeb @ W1[64:128,:] ----
__global__ void k_uv(const float* __restrict__ eW, const float* __restrict__ eb,
                     const float* __restrict__ W1l) {
    int j = threadIdx.x;  // 128
    float u = 0.f, v = 0.f;
    for (int c = 0; c < ED; c++) {
        float wv = W1l[(ED + c) * H2 + j];
        u += eW[c] * wv;
        v += eb[c] * wv;
    }
    g_u[j] = u;
    g_v[j] = v;
}

// ---- scatter-add of gathered node features: aggr[dst] += h[src] (64ch) ----
__global__ void __launch_bounds__(256) k_scatter(const float* __restrict__ h) {
    __shared__ int sSrc[512], sDst[512];
    long long base = (long long)blockIdx.x * 512;   // graph boundary 512-aligned
    int b = (int)(base / EE);
    for (int i = threadIdx.x; i < 512; i += 256) {
        sSrc[i] = g_src[base + i];
        sDst[i] = g_dst[base + i];
    }
    __syncthreads();
    const float* hb = h + (long long)b * NN * ED;
    float* ab = g_aggr + (long long)b * NN * ED;
    int q4 = (threadIdx.x & 15) * 4;
    int l0 = threadIdx.x >> 4;
#pragma unroll 4
    for (int it = 0; it < 32; ++it) {
        int le = l0 + it * 16;
        int src = sSrc[le], dst = sDst[le];
        float4 v = *(const float4*)(hb + src * ED + q4);
        float* p = ab + dst * ED + q4;
        asm volatile("red.global.add.v4.f32 [%0], {%1,%2,%3,%4};"
                     :: "l"(p), "f"(v.x), "f"(v.y), "f"(v.z), "f"(v.w)
                     : "memory");
    }
}

// ---- GEMM1: h2 = aggr(K=64) @ W1[0:64,:] + s*u + deg*v + b1; fused BN stats ----
#define G1_SMEMF (8192 + 64*68 + 64 + 64 + 128*5)
__global__ void __launch_bounds__(256) k_gemm1(const float* __restrict__ W1l,
                                               const float* __restrict__ b1l) {
    extern __shared__ float sm[];
    float* sW   = sm;                  // 64 x 128
    float* sIn  = sW + 8192;           // 64 x 68 (padded)
    float* sS   = sIn + 64 * 68;
    float* sD   = sS + 64;
    float* sU   = sD + 64;
    float* sV   = sU + 128;
    float* sB   = sV + 128;
    float* sSum = sB + 128;
    float* sSqs = sSum + 128;

    int tid = threadIdx.x;
    int b = blockIdx.y;
    int row0 = blockIdx.x * 64;
    int nrows = NN - row0; if (nrows > 64) nrows = 64;

    for (int i = tid; i < 2048; i += 256) ((float4*)sW)[i] = ((const float4*)W1l)[i]; // first 64 rows
    for (int i = tid; i < 128; i += 256) {
        sU[i] = g_u[i]; sV[i] = g_v[i]; sB[i] = b1l[i];
        sSum[i] = 0.f; sSqs[i] = 0.f;
    }
    const float* abase = g_aggr + ((long long)b * NN + row0) * ED;
    for (int i = tid; i < 1024; i += 256) {       // 64 rows x 16 quads
        int r = i >> 4, k4 = i & 15;
        float4 v = (r < nrows) ? ((const float4*)abase)[r * 16 + k4]
                               : make_float4(0.f, 0.f, 0.f, 0.f);
        *(float4*)(sIn + r * 68 + k4 * 4) = v;
    }
    for (int i = tid; i < 64; i += 256) {
        sS[i] = (i < nrows) ? g_s[b * NN + row0 + i] : 0.f;
        sD[i] = (i < nrows) ? g_deg[b * NN + row0 + i] : 0.f;
    }
    __syncthreads();

    int cq = tid & 31, rg = tid >> 5;
    float acc[8][4];
#pragma unroll
    for (int r = 0; r < 8; r++) { acc[r][0]=0.f; acc[r][1]=0.f; acc[r][2]=0.f; acc[r][3]=0.f; }
    const float* inRow = sIn + rg * 8 * 68;
#pragma unroll 8
    for (int k = 0; k < 64; k++) {
        float4 w = *(const float4*)(sW + k * 128 + cq * 4);
#pragma unroll
        for (int r = 0; r < 8; r++) {
            float a = inRow[r * 68 + k];
            acc[r][0] += a * w.x; acc[r][1] += a * w.y;
            acc[r][2] += a * w.z; acc[r][3] += a * w.w;
        }
    }
    float u0 = sU[cq*4], u1 = sU[cq*4+1], u2 = sU[cq*4+2], u3 = sU[cq*4+3];
    float v0 = sV[cq*4], v1 = sV[cq*4+1], v2 = sV[cq*4+2], v3 = sV[cq*4+3];
    float bb0 = sB[cq*4], bb1 = sB[cq*4+1], bb2 = sB[cq*4+2], bb3 = sB[cq*4+3];
    float ps0=0,ps1=0,ps2=0,ps3=0, pq0=0,pq1=0,pq2=0,pq3=0;
    float* obase = g_h2 + ((long long)b * NN + row0) * H2;
#pragma unroll
    for (int r = 0; r < 8; r++) {
        int rr = rg * 8 + r;
        if (rr < nrows) {
            float s = sS[rr], d = sD[rr];
            float o0 = acc[r][0] + s*u0 + d*v0 + bb0;
            float o1 = acc[r][1] + s*u1 + d*v1 + bb1;
            float o2 = acc[r][2] + s*u2 + d*v2 + bb2;
            float o3 = acc[r][3] + s*u3 + d*v3 + bb3;
            float4 o = {o0, o1, o2, o3};
            *(float4*)(obase + rr * H2 + cq * 4) = o;
            ps0 += o0; ps1 += o1; ps2 += o2; ps3 += o3;
            pq0 += o0*o0; pq1 += o1*o1; pq2 += o2*o2; pq3 += o3*o3;
        }
    }
    atomicAdd(sSum + cq*4,     ps0); atomicAdd(sSum + cq*4 + 1, ps1);
    atomicAdd(sSum + cq*4 + 2, ps2); atomicAdd(sSum + cq*4 + 3, ps3);
    atomicAdd(sSqs + cq*4,     pq0); atomicAdd(sSqs + cq*4 + 1, pq1);
    atomicAdd(sSqs + cq*4 + 2, pq2); atomicAdd(sSqs + cq*4 + 3, pq3);
    __syncthreads();
    for (int i = tid; i < 128; i += 256) {
        atomicAdd(&g_sum[b * H2 + i],   sSum[i]);
        atomicAdd(&g_sumsq[b * H2 + i], sSqs[i]);
    }
}

// ---- BN finalize: a = gamma*rsqrt(var+eps), c = beta - mean*a ----
__global__ void k_bnfin(const float* __restrict__ gm, const float* __restrict__ bt) {
    int i = blockIdx.x * 256 + threadIdx.x;
    if (i >= BB * H2) return;
    int c = i & (H2 - 1);
    float mean = g_sum[i] * (1.0f / NN);
    float var  = g_sumsq[i] * (1.0f / NN) - mean * mean;
    float a = gm[c] * rsqrtf(var + BN_EPS);
    g_bnA[i] = a;
    g_bnC[i] = bt[c] - mean * a;
}

// ---- GEMM2: out = relu?(relu(BN(h2)) @ W2 + b2) ----
#define G2_SMEMF (8192 + 64*132)
__global__ void __launch_bounds__(256) k_gemm2(const float* __restrict__ W2l,
                                               const float* __restrict__ b2l,
                                               float* __restrict__ hout, int relu_out) {
    extern __shared__ float sm[];
    float* sW  = sm;           // 128 x 64
    float* sIn = sW + 8192;    // 64 x 132 (padded)
    int tid = threadIdx.x, b = blockIdx.y;
    int row0 = blockIdx.x * 64;
    int nrows = NN - row0; if (nrows > 64) nrows = 64;

    for (int i = tid; i < 2048; i += 256) ((float4*)sW)[i] = ((const float4*)W2l)[i];
    const float* ibase = g_h2 + ((long long)b * NN + row0) * H2;
    const float* A = g_bnA + b * H2;
    const float* C = g_bnC + b * H2;
    for (int i = tid; i < 2048; i += 256) {       // 64 rows x 32 quads
        int r = i >> 5, k4 = i & 31;
        float4 v;
        if (r < nrows) {
            v = ((const float4*)ibase)[r * 32 + k4];
            float4 a4 = ((const float4*)A)[k4];
            float4 c4 = ((const float4*)C)[k4];
            v.x = fmaxf(v.x * a4.x + c4.x, 0.f);
            v.y = fmaxf(v.y * a4.y + c4.y, 0.f);
            v.z = fmaxf(v.z * a4.z + c4.z, 0.f);
            v.w = fmaxf(v.w * a4.w + c4.w, 0.f);
        } else v = make_float4(0.f, 0.f, 0.f, 0.f);
        *(float4*)(sIn + r * 132 + k4 * 4) = v;
    }
    __syncthreads();

    int cq = tid & 15, rg = tid >> 4;   // 16 row-groups x 4 rows = 64 rows
    float acc[4][4];
#pragma unroll
    for (int r = 0; r < 4; r++) { acc[r][0]=0.f; acc[r][1]=0.f; acc[r][2]=0.f; acc[r][3]=0.f; }
    const float* inRow = sIn + rg * 4 * 132;
#pragma unroll 8
    for (int k = 0; k < 128; k++) {
        float4 w = *(const float4*)(sW + k * 64 + cq * 4);
#pragma unroll
        for (int r = 0; r < 4; r++) {
            float a = inRow[r * 132 + k];
            acc[r][0] += a * w.x; acc[r][1] += a * w.y;
            acc[r][2] += a * w.z; acc[r][3] += a * w.w;
        }
    }
    float4 bb = ((const float4*)b2l)[cq];
    float* obase = hout + ((long long)b * NN + row0) * ED;
#pragma unroll
    for (int r = 0; r < 4; r++) {
        int rr = rg * 4 + r;
        if (rr < nrows) {
            float4 o = {acc[r][0] + bb.x, acc[r][1] + bb.y,
                        acc[r][2] + bb.z, acc[r][3] + bb.w};
            if (relu_out) {
                o.x = fmaxf(o.x, 0.f); o.y = fmaxf(o.y, 0.f);
                o.z = fmaxf(o.z, 0.f); o.w = fmaxf(o.w, 0.f);
            }
            *(float4*)(obase + rr * ED + cq * 4) = o;
        }
    }
}

extern "C" void kernel_launch(void* const* d_in, const int* in_sizes, int n_in,
                              void* d_out, int out_size) {
    const float* x     = (const float*)d_in[0];
    const void*  ei    = d_in[1];
    const float* ea    = (const float*)d_in[2];
    const float* inW   = (const float*)d_in[3];
    const float* inb   = (const float*)d_in[4];
    const float* edgeW = (const float*)d_in[5];
    const float* edgeb = (const float*)d_in[6];
    const float* W1    = (const float*)d_in[7];
    const float* b1    = (const float*)d_in[8];
    const float* gamma = (const float*)d_in[9];
    const float* beta  = (const float*)d_in[10];
    const float* W2    = (const float*)d_in[11];
    const float* b2    = (const float*)d_in[12];
    float* out = (float*)d_out;

    void *ps, *pd, *pa, *psum, *psq, *ph0, *ph1;
    cudaGetSymbolAddress(&ps, g_s);
    cudaGetSymbolAddress(&pd, g_deg);
    cudaGetSymbolAddress(&pa, g_aggr);
    cudaGetSymbolAddress(&psum, g_sum);
    cudaGetSymbolAddress(&psq, g_sumsq);
    cudaGetSymbolAddress(&ph0, g_h0);
    cudaGetSymbolAddress(&ph1, g_h1);

    cudaFuncSetAttribute(k_gemm1, cudaFuncAttributeMaxDynamicSharedMemorySize, G1_SMEMF * 4);
    cudaFuncSetAttribute(k_gemm2, cudaFuncAttributeMaxDynamicSharedMemorySize, G2_SMEMF * 4);

    cudaMemsetAsync(ps, 0, BB * NN * sizeof(float));
    cudaMemsetAsync(pd, 0, BB * NN * sizeof(float));
    k_detect<<<1, 256>>>((const unsigned int*)ei);
    k_prep<<<(BB * EE + 255) / 256, 256>>>(ei, ea);
    k_embed<<<BB * NN / 4, 256>>>(x, inW, inb);

    const float* hin = (const float*)ph0;
    dim3 gGemm((NN + 63) / 64, BB);
    for (int l = 0; l < NL; l++) {
        k_uv<<<1, 128>>>(edgeW + l * ED, edgeb + l * ED, W1 + l * H2 * H2);
        cudaMemsetAsync(pa, 0, (size_t)HSZ * sizeof(float));
        k_scatter<<<BB * EE / 512, 256>>>(hin);
        cudaMemsetAsync(psum, 0, BB * H2 * sizeof(float));
        cudaMemsetAsync(psq, 0, BB * H2 * sizeof(float));
        k_gemm1<<<gGemm, 256, G1_SMEMF * 4>>>(W1 + l * H2 * H2, b1 + l * H2);
        k_bnfin<<<2, 256>>>(gamma + l * H2, beta + l * H2);
        float* hout = (l == NL - 1) ? out : ((l == 0) ? (float*)ph1 : (float*)ph0);
        k_gemm2<<<gGemm, 256, G2_SMEMF * 4>>>(W2 + l * H2 * ED, b2 + l * ED, hout,
                                              (l < NL - 1) ? 1 : 0);
        hin = hout;
    }
}

// round 4
// speedup vs baseline: 1.2018x; 1.2018x over previous
#include <cuda_runtime.h>

#define BB 4
#define NN 20000
#define EE 320000
#define IND 21
#define ED 64
#define H2 128
#define NL 3
#define BN_EPS 1e-5f

#define HSZ  (BB*NN*ED)
#define H2SZ (BB*NN*H2)

// ---- zero-initialized-per-launch scratch, one memset ----
struct ZBuf {
    float s[BB*NN];
    int   cnt[BB*NN];
    int   fill[BB*NN];
    int   ctr[BB];
    float sum[NL*BB*H2];
    float sumsq[NL*BB*H2];
};
__device__ ZBuf gz;

__device__ int   g_src[BB*EE];
__device__ int   g_dst[BB*EE];
__device__ int   g_off[BB*NN];
__device__ int   g_csr[BB*EE];
__device__ float g_h0[HSZ];
__device__ float g_h1[HSZ];
__device__ float g_h2[H2SZ];
__device__ float g_u[NL*H2];
__device__ float g_v[NL*H2];
__device__ int   g_is64;

// ---- dtype detection: int64 edge_index has all-zero high words ----
__global__ void k_detect(const unsigned int* __restrict__ ei32) {
    __shared__ unsigned int sOr[256];
    sOr[threadIdx.x] = ei32[2 * threadIdx.x + 1];
    __syncthreads();
    for (int s = 128; s > 0; s >>= 1) {
        if (threadIdx.x < s) sOr[threadIdx.x] |= sOr[threadIdx.x + s];
        __syncthreads();
    }
    if (threadIdx.x == 0) g_is64 = (sOr[0] == 0) ? 1 : 0;
}

// ---- decode indices + per-node edge-attr sum + in-degree count ----
__global__ void __launch_bounds__(256) k_prep(const void* __restrict__ ei,
                                              const float* __restrict__ ea) {
    int idx = blockIdx.x * 256 + threadIdx.x;
    int b = idx / EE;
    int e = idx - b * EE;
    int src, dst;
    if (g_is64) {
        const long long* p = (const long long*)ei + (long long)b * 2 * EE;
        src = (int)p[e];
        dst = (int)p[EE + e];
    } else {
        const int* p = (const int*)ei + (long long)b * 2 * EE;
        src = p[e];
        dst = p[EE + e];
    }
    g_src[idx] = src;
    g_dst[idx] = dst;
    atomicAdd(&gz.s[b * NN + dst], ea[idx]);
    atomicAdd(&gz.cnt[b * NN + dst], 1);
}

// ---- CSR offsets (unordered partition) + all-layer rank-2 uv fold ----
#define OFF_BLOCKS ((BB*NN + 255) / 256)   // 313
__global__ void __launch_bounds__(256) k_offuv(const float* __restrict__ edgeW,
                                               const float* __restrict__ edgeb,
                                               const float* __restrict__ W1) {
    if (blockIdx.x < OFF_BLOCKS) {
        int i = blockIdx.x * 256 + threadIdx.x;
        if (i < BB * NN) {
            int b = i / NN;
            int c = gz.cnt[i];
            int o = atomicAdd(&gz.ctr[b], c);
            g_off[i] = b * EE + o;
        }
    } else {
        int l = blockIdx.x - OFF_BLOCKS;           // 0..NL-1
        __shared__ float su[2][128], sv[2][128];
        int j = threadIdx.x & 127, hf = threadIdx.x >> 7;
        const float* Wl = W1 + l * H2 * H2;
        float u = 0.f, v = 0.f;
#pragma unroll 8
        for (int c = hf * 32; c < hf * 32 + 32; c++) {
            float wv = Wl[(ED + c) * H2 + j];
            u += edgeW[l * ED + c] * wv;
            v += edgeb[l * ED + c] * wv;
        }
        su[hf][j] = u; sv[hf][j] = v;
        __syncthreads();
        if (hf == 0) {
            g_u[l * H2 + j] = su[0][j] + su[1][j];
            g_v[l * H2 + j] = sv[0][j] + sv[1][j];
        }
    }
}

// ---- CSR placement + input embedding (fused, disjoint block ranges) ----
#define PLACE_BLOCKS (BB*EE / 256)   // 5000
#define EMB_BLOCKS   (BB*NN / 64)    // 1250
__global__ void __launch_bounds__(256) k_place(const float* __restrict__ x,
                                               const float* __restrict__ inW,
                                               const float* __restrict__ inb) {
    if (blockIdx.x < PLACE_BLOCKS) {
        int idx = blockIdx.x * 256 + threadIdx.x;
        int b = idx / EE;
        int dst = g_dst[idx];
        int r = atomicAdd(&gz.fill[b * NN + dst], 1);
        g_csr[g_off[b * NN + dst] + r] = g_src[idx];
    } else {
        __shared__ float sW[IND * ED];
        __shared__ float sX[64 * IND];
        int nid0 = (blockIdx.x - PLACE_BLOCKS) * 64;
        int tid = threadIdx.x;
        for (int i = tid; i < IND * ED; i += 256) sW[i] = inW[i];
        for (int i = tid; i < 64 * IND; i += 256) sX[i] = x[(long long)nid0 * IND + i];
        __syncthreads();
        int j = tid & 63;
        float bj = inb[j];
        for (int loc = tid >> 6; loc < 64; loc += 4) {
            float acc = bj;
#pragma unroll
            for (int i = 0; i < IND; i++) acc += sX[loc * IND + i] * sW[i * ED + j];
            g_h0[(long long)(nid0 + loc) * ED + j] = acc;
        }
    }
}

// ---- GEMM1 (fused gather-aggregate): h2 = seg_sum(h[src]) @ W1[0:64,:]
//      + s*u + deg*v + b1 ; fused BN-stat reduction ----
#define G1_SMEMF (8192 + 64*68 + 64*3 + 128*5)
__global__ void __launch_bounds__(256) k_gemm1(const float* __restrict__ W1l,
                                               const float* __restrict__ b1l,
                                               const float* __restrict__ hin,
                                               int l) {
    extern __shared__ float sm[];
    float* sW   = sm;                  // 64 x 128
    float* sIn  = sW + 8192;           // 64 x 68 (padded)
    float* sS   = sIn + 64 * 68;
    int*   sOff = (int*)(sS + 64);
    int*   sCnt = sOff + 64;
    float* sU   = (float*)(sCnt + 64);
    float* sV   = sU + 128;
    float* sB   = sV + 128;
    float* sSum = sB + 128;
    float* sSqs = sSum + 128;

    int tid = threadIdx.x;
    int b = blockIdx.y;
    int row0 = blockIdx.x * 64;
    int nrows = NN - row0; if (nrows > 64) nrows = 64;

    for (int i = tid; i < 2048; i += 256) ((float4*)sW)[i] = ((const float4*)W1l)[i];
    for (int i = tid; i < 128; i += 256) {
        sU[i] = g_u[l * H2 + i]; sV[i] = g_v[l * H2 + i]; sB[i] = b1l[i];
        sSum[i] = 0.f; sSqs[i] = 0.f;
    }
    if (tid < 64) {
        int ok = tid < nrows;
        int i = b * NN + row0 + tid;
        sOff[tid] = ok ? g_off[i] : 0;
        sCnt[tid] = ok ? gz.cnt[i] : 0;
        sS[tid]   = ok ? gz.s[i] : 0.f;
    }
    __syncthreads();

    // gather + segment-sum straight from h (no aggr buffer, no atomics)
    {
        int q4 = (tid & 15) * 4;
        int g = tid >> 4;
        const float* hb = hin + (long long)b * NN * ED;
#pragma unroll
        for (int rr = g * 4; rr < g * 4 + 4; rr++) {
            int off = sOff[rr], c = sCnt[rr];
            float ax = 0.f, ay = 0.f, az = 0.f, aw = 0.f;
            for (int e = 0; e < c; e++) {
                int src = g_csr[off + e];
                float4 v = *(const float4*)(hb + (long long)src * ED + q4);
                ax += v.x; ay += v.y; az += v.z; aw += v.w;
            }
            float4 o = {ax, ay, az, aw};
            *(float4*)(sIn + rr * 68 + q4) = o;
        }
    }
    __syncthreads();

    int cq = tid & 31, rg = tid >> 5;
    float acc[8][4];
#pragma unroll
    for (int r = 0; r < 8; r++) { acc[r][0]=0.f; acc[r][1]=0.f; acc[r][2]=0.f; acc[r][3]=0.f; }
    const float* inRow = sIn + rg * 8 * 68;
#pragma unroll 8
    for (int k = 0; k < 64; k++) {
        float4 w = *(const float4*)(sW + k * 128 + cq * 4);
#pragma unroll
        for (int r = 0; r < 8; r++) {
            float a = inRow[r * 68 + k];
            acc[r][0] += a * w.x; acc[r][1] += a * w.y;
            acc[r][2] += a * w.z; acc[r][3] += a * w.w;
        }
    }
    float u0 = sU[cq*4], u1 = sU[cq*4+1], u2 = sU[cq*4+2], u3 = sU[cq*4+3];
    float v0 = sV[cq*4], v1 = sV[cq*4+1], v2 = sV[cq*4+2], v3 = sV[cq*4+3];
    float bb0 = sB[cq*4], bb1 = sB[cq*4+1], bb2 = sB[cq*4+2], bb3 = sB[cq*4+3];
    float ps0=0,ps1=0,ps2=0,ps3=0, pq0=0,pq1=0,pq2=0,pq3=0;
    float* obase = g_h2 + ((long long)b * NN + row0) * H2;
#pragma unroll
    for (int r = 0; r < 8; r++) {
        int rr = rg * 8 + r;
        if (rr < nrows) {
            float s = sS[rr], d = (float)sCnt[rr];
            float o0 = acc[r][0] + s*u0 + d*v0 + bb0;
            float o1 = acc[r][1] + s*u1 + d*v1 + bb1;
            float o2 = acc[r][2] + s*u2 + d*v2 + bb2;
            float o3 = acc[r][3] + s*u3 + d*v3 + bb3;
            float4 o = {o0, o1, o2, o3};
            *(float4*)(obase + rr * H2 + cq * 4) = o;
            ps0 += o0; ps1 += o1; ps2 += o2; ps3 += o3;
            pq0 += o0*o0; pq1 += o1*o1; pq2 += o2*o2; pq3 += o3*o3;
        }
    }
    atomicAdd(sSum + cq*4,     ps0); atomicAdd(sSum + cq*4 + 1, ps1);
    atomicAdd(sSum + cq*4 + 2, ps2); atomicAdd(sSum + cq*4 + 3, ps3);
    atomicAdd(sSqs + cq*4,     pq0); atomicAdd(sSqs + cq*4 + 1, pq1);
    atomicAdd(sSqs + cq*4 + 2, pq2); atomicAdd(sSqs + cq*4 + 3, pq3);
    __syncthreads();
    float* gsum = gz.sum   + l * BB * H2 + b * H2;
    float* gsq  = gz.sumsq + l * BB * H2 + b * H2;
    for (int i = tid; i < 128; i += 256) {
        atomicAdd(&gsum[i], sSum[i]);
        atomicAdd(&gsq[i],  sSqs[i]);
    }
}

// ---- GEMM2 (BN finalize fused): out = relu?(relu(BN(h2)) @ W2 + b2) ----
#define G2_SMEMF (8192 + 64*132 + 256)
__global__ void __launch_bounds__(256) k_gemm2(const float* __restrict__ W2l,
                                               const float* __restrict__ b2l,
                                               const float* __restrict__ gm,
                                               const float* __restrict__ bt,
                                               float* __restrict__ hout,
                                               int l, int relu_out) {
    extern __shared__ float sm[];
    float* sW  = sm;            // 128 x 64
    float* sIn = sW + 8192;     // 64 x 132 (padded)
    float* sA  = sIn + 64 * 132;
    float* sC  = sA + 128;
    int tid = threadIdx.x, b = blockIdx.y;
    int row0 = blockIdx.x * 64;
    int nrows = NN - row0; if (nrows > 64) nrows = 64;

    for (int i = tid; i < 2048; i += 256) ((float4*)sW)[i] = ((const float4*)W2l)[i];
    const float* gsum = gz.sum   + l * BB * H2 + b * H2;
    const float* gsq  = gz.sumsq + l * BB * H2 + b * H2;
    for (int i = tid; i < 128; i += 256) {
        float mean = gsum[i] * (1.0f / NN);
        float var  = gsq[i] * (1.0f / NN) - mean * mean;
        float a = gm[i] * rsqrtf(var + BN_EPS);
        sA[i] = a;
        sC[i] = bt[i] - mean * a;
    }
    __syncthreads();

    const float* ibase = g_h2 + ((long long)b * NN + row0) * H2;
    for (int i = tid; i < 2048; i += 256) {       // 64 rows x 32 quads
        int r = i >> 5, k4 = i & 31;
        float4 v;
        if (r < nrows) {
            v = ((const float4*)ibase)[r * 32 + k4];
            float4 a4 = ((const float4*)sA)[k4];
            float4 c4 = ((const float4*)sC)[k4];
            v.x = fmaxf(v.x * a4.x + c4.x, 0.f);
            v.y = fmaxf(v.y * a4.y + c4.y, 0.f);
            v.z = fmaxf(v.z * a4.z + c4.z, 0.f);
            v.w = fmaxf(v.w * a4.w + c4.w, 0.f);
        } else v = make_float4(0.f, 0.f, 0.f, 0.f);
        *(float4*)(sIn + r * 132 + k4 * 4) = v;
    }
    __syncthreads();

    int cq = tid & 15, rg = tid >> 4;
    float acc[4][4];
#pragma unroll
    for (int r = 0; r < 4; r++) { acc[r][0]=0.f; acc[r][1]=0.f; acc[r][2]=0.f; acc[r][3]=0.f; }
    const float* inRow = sIn + rg * 4 * 132;
#pragma unroll 8
    for (int k = 0; k < 128; k++) {
        float4 w = *(const float4*)(sW + k * 64 + cq * 4);
#pragma unroll
        for (int r = 0; r < 4; r++) {
            float a = inRow[r * 132 + k];
            acc[r][0] += a * w.x; acc[r][1] += a * w.y;
            acc[r][2] += a * w.z; acc[r][3] += a * w.w;
        }
    }
    float4 bb = ((const float4*)b2l)[cq];
    float* obase = hout + ((long long)b * NN + row0) * ED;
#pragma unroll
    for (int r = 0; r < 4; r++) {
        int rr = rg * 4 + r;
        if (rr < nrows) {
            float4 o = {acc[r][0] + bb.x, acc[r][1] + bb.y,
                        acc[r][2] + bb.z, acc[r][3] + bb.w};
            if (relu_out) {
                o.x = fmaxf(o.x, 0.f); o.y = fmaxf(o.y, 0.f);
                o.z = fmaxf(o.z, 0.f); o.w = fmaxf(o.w, 0.f);
            }
            *(float4*)(obase + rr * ED + cq * 4) = o;
        }
    }
}

extern "C" void kernel_launch(void* const* d_in, const int* in_sizes, int n_in,
                              void* d_out, int out_size) {
    const float* x     = (const float*)d_in[0];
    const void*  ei    = d_in[1];
    const float* ea    = (const float*)d_in[2];
    const float* inW   = (const float*)d_in[3];
    const float* inb   = (const float*)d_in[4];
    const float* edgeW = (const float*)d_in[5];
    const float* edgeb = (const float*)d_in[6];
    const float* W1    = (const float*)d_in[7];
    const float* b1    = (const float*)d_in[8];
    const float* gamma = (const float*)d_in[9];
    const float* beta  = (const float*)d_in[10];
    const float* W2    = (const float*)d_in[11];
    const float* b2    = (const float*)d_in[12];
    float* out = (float*)d_out;

    void *pz, *ph0, *ph1;
    cudaGetSymbolAddress(&pz, gz);
    cudaGetSymbolAddress(&ph0, g_h0);
    cudaGetSymbolAddress(&ph1, g_h1);

    cudaFuncSetAttribute(k_gemm1, cudaFuncAttributeMaxDynamicSharedMemorySize, G1_SMEMF * 4);
    cudaFuncSetAttribute(k_gemm2, cudaFuncAttributeMaxDynamicSharedMemorySize, G2_SMEMF * 4);

    cudaMemsetAsync(pz, 0, sizeof(ZBuf));                       // launch 0 (memset)
    k_detect<<<1, 256>>>((const unsigned int*)ei);              // 1
    k_prep<<<PLACE_BLOCKS, 256>>>(ei, ea);                      // 2
    k_offuv<<<OFF_BLOCKS + NL, 256>>>(edgeW, edgeb, W1);        // 3
    k_place<<<PLACE_BLOCKS + EMB_BLOCKS, 256>>>(x, inW, inb);   // 4

    const float* hin = (const float*)ph0;
    dim3 gGemm((NN + 63) / 64, BB);
    for (int l = 0; l < NL; l++) {
        k_gemm1<<<gGemm, 256, G1_SMEMF * 4>>>(W1 + l * H2 * H2, b1 + l * H2, hin, l); // 5 at l=0
        float* hout = (l == NL - 1) ? out : ((l == 0) ? (float*)ph1 : (float*)ph0);
        k_gemm2<<<gGemm, 256, G2_SMEMF * 4>>>(W2 + l * H2 * ED, b2 + l * ED,
                                              gamma + l * H2, beta + l * H2,
                                              hout, l, (l < NL - 1) ? 1 : 0);
        hin = hout;
    }
}

// round 6
// speedup vs baseline: 1.2187x; 1.0140x over previous
#include <cuda_runtime.h>

#define BB 4
#define NN 20000
#define EE 320000
#define IND 21
#define ED 64
#define H2 128
#define NL 3
#define BN_EPS 1e-5f

#define HSZ  (BB*NN*ED)
#define H2SZ (BB*NN*H2)

// packed fp32x2 helpers (FFMA2 path — bit-exact dual fp32 FMA)
#define FMA2(acc, a, b) \
    asm("fma.rn.f32x2 %0, %1, %2, %0;" : "+l"(acc) : "l"(a), "l"(b))
#define PK2(out, x) \
    asm("mov.b64 %0, {%1, %1};" : "=l"(out) : "r"(__float_as_uint(x)))
#define UNPK(lo, hi, v) \
    { unsigned int _l, _h; asm("mov.b64 {%0, %1}, %2;" : "=r"(_l), "=r"(_h) : "l"(v)); \
      lo = __uint_as_float(_l); hi = __uint_as_float(_h); }

// ---- zero-initialized-per-launch scratch (cleared by k_zero) ----
struct ZBuf {
    float sc[2*BB*NN];     // interleaved {attr-sum, deg} per node
    int   fill[BB*NN];
    int   ctr[BB];
    float sum[NL*BB*H2];
    float sumsq[NL*BB*H2];
};
__device__ ZBuf gz;

__device__ int   g_src[BB*EE];
__device__ int   g_dst[BB*EE];
__device__ int   g_off[BB*NN];
__device__ int   g_csr[BB*EE];
__device__ float g_h0[HSZ];
__device__ float g_h1[HSZ];
__device__ float g_h2[H2SZ];
__device__ float g_u[NL*H2];
__device__ float g_v[NL*H2];
__device__ int   g_is64;

// ---- launch 0: zero scratch (kernel, not memset, for deterministic ncu slots) ----
__global__ void k_zero() {
    int* p = (int*)&gz;
    int n = sizeof(ZBuf) / 4;
    for (int i = blockIdx.x * 256 + threadIdx.x; i < n; i += gridDim.x * 256) p[i] = 0;
}

// ---- launch 1: dtype detection: int64 edge_index has all-zero high words ----
__global__ void k_detect(const unsigned int* __restrict__ ei32) {
    __shared__ unsigned int sOr[256];
    sOr[threadIdx.x] = ei32[2 * threadIdx.x + 1];
    __syncthreads();
    for (int s = 128; s > 0; s >>= 1) {
        if (threadIdx.x < s) sOr[threadIdx.x] |= sOr[threadIdx.x + s];
        __syncthreads();
    }
    if (threadIdx.x == 0) g_is64 = (sOr[0] == 0) ? 1 : 0;
}

// ---- launch 2: decode indices + per-node {attr-sum, deg} via one v2 reduction ----
__global__ void __launch_bounds__(256) k_prep(const void* __restrict__ ei,
                                              const float* __restrict__ ea) {
    int idx = blockIdx.x * 256 + threadIdx.x;
    int b = idx / EE;
    int e = idx - b * EE;
    int src, dst;
    if (g_is64) {
        const long long* p = (const long long*)ei + (long long)b * 2 * EE;
        src = (int)p[e];
        dst = (int)p[EE + e];
    } else {
        const int* p = (const int*)ei + (long long)b * 2 * EE;
        src = p[e];
        dst = p[EE + e];
    }
    g_src[idx] = src;
    g_dst[idx] = dst;
    float* p2 = &gz.sc[2 * (b * NN + dst)];
    float a = ea[idx];
    asm volatile("red.global.add.v2.f32 [%0], {%1,%2};"
                 :: "l"(p2), "f"(a), "f"(1.0f) : "memory");
}

// ---- launch 3: CSR offsets (unordered partition) + all-layer rank-2 uv fold ----
#define OFF_BLOCKS ((BB*NN + 255) / 256)   // 313
__global__ void __launch_bounds__(256) k_offuv(const float* __restrict__ edgeW,
                                               const float* __restrict__ edgeb,
                                               const float* __restrict__ W1) {
    if (blockIdx.x < OFF_BLOCKS) {
        int i = blockIdx.x * 256 + threadIdx.x;
        if (i < BB * NN) {
            int b = i / NN;
            int c = (int)gz.sc[2 * i + 1];
            int o = atomicAdd(&gz.ctr[b], c);
            g_off[i] = b * EE + o;
        }
    } else {
        int l = blockIdx.x - OFF_BLOCKS;           // 0..NL-1
        __shared__ float su[2][128], sv[2][128];
        int j = threadIdx.x & 127, hf = threadIdx.x >> 7;
        const float* Wl = W1 + l * H2 * H2;
        float u = 0.f, v = 0.f;
#pragma unroll 8
        for (int c = hf * 32; c < hf * 32 + 32; c++) {
            float wv = Wl[(ED + c) * H2 + j];
            u += edgeW[l * ED + c] * wv;
            v += edgeb[l * ED + c] * wv;
        }
        su[hf][j] = u; sv[hf][j] = v;
        __syncthreads();
        if (hf == 0) {
            g_u[l * H2 + j] = su[0][j] + su[1][j];
            g_v[l * H2 + j] = sv[0][j] + sv[1][j];
        }
    }
}

// ---- launch 4: CSR placement + input embedding (fused, disjoint block ranges) ----
#define PLACE_BLOCKS (BB*EE / 256)   // 5000
#define EMB_BLOCKS   (BB*NN / 64)    // 1250
__global__ void __launch_bounds__(256) k_place(const float* __restrict__ x,
                                               const float* __restrict__ inW,
                                               const float* __restrict__ inb) {
    if (blockIdx.x < PLACE_BLOCKS) {
        int idx = blockIdx.x * 256 + threadIdx.x;
        int b = idx / EE;
        int dst = g_dst[idx];
        int r = atomicAdd(&gz.fill[b * NN + dst], 1);
        g_csr[g_off[b * NN + dst] + r] = g_src[idx];
    } else {
        __shared__ float sW[IND * ED];
        __shared__ float sX[64 * IND];
        int nid0 = (blockIdx.x - PLACE_BLOCKS) * 64;
        int tid = threadIdx.x;
        for (int i = tid; i < IND * ED; i += 256) sW[i] = inW[i];
        for (int i = tid; i < 64 * IND; i += 256) sX[i] = x[(long long)nid0 * IND + i];
        __syncthreads();
        int j = tid & 63;
        float bj = inb[j];
        for (int loc = tid >> 6; loc < 64; loc += 4) {
            float acc = bj;
#pragma unroll
            for (int i = 0; i < IND; i++) acc += sX[loc * IND + i] * sW[i * ED + j];
            g_h0[(long long)(nid0 + loc) * ED + j] = acc;
        }
    }
}

// ---- launch 5: GEMM1 (fused gather-aggregate, FFMA2 mainloop):
//      h2 = seg_sum(h[src]) @ W1[0:64,:] + s*u + deg*v + b1 ; fused BN stats ----
#define ST1 66
#define G1_SMEMF (8192 + 64*ST1 + 64 + 64 + 64 + 128*5)
__global__ void __launch_bounds__(256) k_gemm1(const float* __restrict__ W1l,
                                               const float* __restrict__ b1l,
                                               const float* __restrict__ hin,
                                               int l) {
    extern __shared__ float sm[];
    float* sW   = sm;                  // 64 x 128
    float* sInT = sW + 8192;           // 64 k x 66 rows (transposed, 8B-aligned pairs)
    float* sS   = sInT + 64 * ST1;
    int*   sOff = (int*)(sS + 64);
    int*   sCnt = sOff + 64;
    float* sU   = (float*)(sCnt + 64);
    float* sV   = sU + 128;
    float* sB   = sV + 128;
    float* sSum = sB + 128;
    float* sSqs = sSum + 128;

    int tid = threadIdx.x;
    int b = blockIdx.y;
    int row0 = blockIdx.x * 64;
    int nrows = NN - row0; if (nrows > 64) nrows = 64;

    for (int i = tid; i < 2048; i += 256) ((float4*)sW)[i] = ((const float4*)W1l)[i];
    for (int i = tid; i < 128; i += 256) {
        sU[i] = g_u[l * H2 + i]; sV[i] = g_v[l * H2 + i]; sB[i] = b1l[i];
        sSum[i] = 0.f; sSqs[i] = 0.f;
    }
    if (tid < 64) {
        int ok = tid < nrows;
        int i = b * NN + row0 + tid;
        sOff[tid] = ok ? g_off[i] : 0;
        sCnt[tid] = ok ? (int)gz.sc[2 * i + 1] : 0;
        sS[tid]   = ok ? gz.sc[2 * i] : 0.f;
    }
    __syncthreads();

    // gather + segment-sum straight from h; write TRANSPOSED into sInT[k][row]
    {
        int q4 = (tid & 15) * 4;
        int g = tid >> 4;
        const float* hb = hin + (long long)b * NN * ED;
#pragma unroll
        for (int rr = g * 4; rr < g * 4 + 4; rr++) {
            int off = sOff[rr], c = sCnt[rr];
            float ax = 0.f, ay = 0.f, az = 0.f, aw = 0.f;
            for (int e = 0; e < c; e++) {
                int src = g_csr[off + e];
                float4 v = *(const float4*)(hb + (long long)src * ED + q4);
                ax += v.x; ay += v.y; az += v.z; aw += v.w;
            }
            sInT[(q4 + 0) * ST1 + rr] = ax;
            sInT[(q4 + 1) * ST1 + rr] = ay;
            sInT[(q4 + 2) * ST1 + rr] = az;
            sInT[(q4 + 3) * ST1 + rr] = aw;
        }
    }
    __syncthreads();

    int cq = tid & 31, rg = tid >> 5;   // 32 colquads x 8 rowgroups(8 rows)
    unsigned long long acc2[4][4];      // [rowpair][col]
#pragma unroll
    for (int p = 0; p < 4; p++)
        acc2[p][0] = acc2[p][1] = acc2[p][2] = acc2[p][3] = 0ull;

#pragma unroll 8
    for (int k = 0; k < 64; k++) {
        float4 w = *(const float4*)(sW + k * 128 + cq * 4);
        unsigned long long wb0, wb1, wb2, wb3;
        PK2(wb0, w.x); PK2(wb1, w.y); PK2(wb2, w.z); PK2(wb3, w.w);
        const unsigned long long* arow =
            (const unsigned long long*)(sInT + k * ST1 + rg * 8);
#pragma unroll
        for (int p = 0; p < 4; p++) {
            unsigned long long ap = arow[p];
            FMA2(acc2[p][0], ap, wb0);
            FMA2(acc2[p][1], ap, wb1);
            FMA2(acc2[p][2], ap, wb2);
            FMA2(acc2[p][3], ap, wb3);
        }
    }

    float u0 = sU[cq*4], u1 = sU[cq*4+1], u2 = sU[cq*4+2], u3 = sU[cq*4+3];
    float v0 = sV[cq*4], v1 = sV[cq*4+1], v2 = sV[cq*4+2], v3 = sV[cq*4+3];
    float bb0 = sB[cq*4], bb1 = sB[cq*4+1], bb2 = sB[cq*4+2], bb3 = sB[cq*4+3];
    float ps0=0,ps1=0,ps2=0,ps3=0, pq0=0,pq1=0,pq2=0,pq3=0;
    float* obase = g_h2 + ((long long)b * NN + row0) * H2;
#pragma unroll
    for (int p = 0; p < 4; p++) {
        float o_[2][4];
        UNPK(o_[0][0], o_[1][0], acc2[p][0]);
        UNPK(o_[0][1], o_[1][1], acc2[p][1]);
        UNPK(o_[0][2], o_[1][2], acc2[p][2]);
        UNPK(o_[0][3], o_[1][3], acc2[p][3]);
#pragma unroll
        for (int t = 0; t < 2; t++) {
            int rr = rg * 8 + 2 * p + t;
            if (rr < nrows) {
                float s = sS[rr], d = (float)sCnt[rr];
                float o0 = o_[t][0] + s*u0 + d*v0 + bb0;
                float o1 = o_[t][1] + s*u1 + d*v1 + bb1;
                float o2 = o_[t][2] + s*u2 + d*v2 + bb2;
                float o3 = o_[t][3] + s*u3 + d*v3 + bb3;
                float4 o = {o0, o1, o2, o3};
                *(float4*)(obase + rr * H2 + cq * 4) = o;
                ps0 += o0; ps1 += o1; ps2 += o2; ps3 += o3;
                pq0 += o0*o0; pq1 += o1*o1; pq2 += o2*o2; pq3 += o3*o3;
            }
        }
    }
    atomicAdd(sSum + cq*4,     ps0); atomicAdd(sSum + cq*4 + 1, ps1);
    atomicAdd(sSum + cq*4 + 2, ps2); atomicAdd(sSum + cq*4 + 3, ps3);
    atomicAdd(sSqs + cq*4,     pq0); atomicAdd(sSqs + cq*4 + 1, pq1);
    atomicAdd(sSqs + cq*4 + 2, pq2); atomicAdd(sSqs + cq*4 + 3, pq3);
    __syncthreads();
    float* gsum = gz.sum   + l * BB * H2 + b * H2;
    float* gsq  = gz.sumsq + l * BB * H2 + b * H2;
    for (int i = tid; i < 128; i += 256) {
        atomicAdd(&gsum[i], sSum[i]);
        atomicAdd(&gsq[i],  sSqs[i]);
    }
}

// ---- GEMM2 (BN finalize fused, FFMA2 mainloop): out = relu?(relu(BN(h2)) @ W2 + b2) ----
#define ST2 66
#define G2_SMEMF (8192 + 128*ST2 + 256)
__global__ void __launch_bounds__(256) k_gemm2(const float* __restrict__ W2l,
                                               const float* __restrict__ b2l,
                                               const float* __restrict__ gm,
                                               const float* __restrict__ bt,
                                               float* __restrict__ hout,
                                               int l, int relu_out) {
    extern __shared__ float sm[];
    float* sW   = sm;             // 128 x 64
    float* sInT = sW + 8192;      // 128 k x 66 rows (transposed)
    float* sA   = sInT + 128 * ST2;
    float* sC   = sA + 128;
    int tid = threadIdx.x, b = blockIdx.y;
    int row0 = blockIdx.x * 64;
    int nrows = NN - row0; if (nrows > 64) nrows = 64;

    for (int i = tid; i < 2048; i += 256) ((float4*)sW)[i] = ((const float4*)W2l)[i];
    const float* gsum = gz.sum   + l * BB * H2 + b * H2;
    const float* gsq  = gz.sumsq + l * BB * H2 + b * H2;
    for (int i = tid; i < 128; i += 256) {
        float mean = gsum[i] * (1.0f / NN);
        float var  = gsq[i] * (1.0f / NN) - mean * mean;
        float a = gm[i] * rsqrtf(var + BN_EPS);
        sA[i] = a;
        sC[i] = bt[i] - mean * a;
    }
    __syncthreads();

    // stage BN(h2)+relu TRANSPOSED: i -> r = i&63 (warp-consecutive => conflict-free STS)
    const float* ibase = g_h2 + ((long long)b * NN + row0) * H2;
    for (int i = tid; i < 2048; i += 256) {
        int r = i & 63, k4 = i >> 6;   // k4 in 0..31
        float4 v;
        if (r < nrows) {
            v = ((const float4*)ibase)[r * 32 + k4];
            float4 a4 = ((const float4*)sA)[k4];
            float4 c4 = ((const float4*)sC)[k4];
            v.x = fmaxf(v.x * a4.x + c4.x, 0.f);
            v.y = fmaxf(v.y * a4.y + c4.y, 0.f);
            v.z = fmaxf(v.z * a4.z + c4.z, 0.f);
            v.w = fmaxf(v.w * a4.w + c4.w, 0.f);
        } else v = make_float4(0.f, 0.f, 0.f, 0.f);
        sInT[(k4 * 4 + 0) * ST2 + r] = v.x;
        sInT[(k4 * 4 + 1) * ST2 + r] = v.y;
        sInT[(k4 * 4 + 2) * ST2 + r] = v.z;
        sInT[(k4 * 4 + 3) * ST2 + r] = v.w;
    }
    __syncthreads();

    int cq = tid & 15, rg = tid >> 4;   // 16 colquads x 16 rowgroups(4 rows)
    unsigned long long acc2[2][4];
#pragma unroll
    for (int p = 0; p < 2; p++)
        acc2[p][0] = acc2[p][1] = acc2[p][2] = acc2[p][3] = 0ull;

#pragma unroll 8
    for (int k = 0; k < 128; k++) {
        float4 w = *(const float4*)(sW + k * 64 + cq * 4);
        unsigned long long wb0, wb1, wb2, wb3;
        PK2(wb0, w.x); PK2(wb1, w.y); PK2(wb2, w.z); PK2(wb3, w.w);
        const unsigned long long* arow =
            (const unsigned long long*)(sInT + k * ST2 + rg * 4);
#pragma unroll
        for (int p = 0; p < 2; p++) {
            unsigned long long ap = arow[p];
            FMA2(acc2[p][0], ap, wb0);
            FMA2(acc2[p][1], ap, wb1);
            FMA2(acc2[p][2], ap, wb2);
            FMA2(acc2[p][3], ap, wb3);
        }
    }

    float4 bb = ((const float4*)b2l)[cq];
    float* obase = hout + ((long long)b * NN + row0) * ED;
#pragma unroll
    for (int p = 0; p < 2; p++) {
        float o_[2][4];
        UNPK(o_[0][0], o_[1][0], acc2[p][0]);
        UNPK(o_[0][1], o_[1][1], acc2[p][1]);
        UNPK(o_[0][2], o_[1][2], acc2[p][2]);
        UNPK(o_[0][3], o_[1][3], acc2[p][3]);
#pragma unroll
        for (int t = 0; t < 2; t++) {
            int rr = rg * 4 + 2 * p + t;
            if (rr < nrows) {
                float4 o = {o_[t][0] + bb.x, o_[t][1] + bb.y,
                            o_[t][2] + bb.z, o_[t][3] + bb.w};
                if (relu_out) {
                    o.x = fmaxf(o.x, 0.f); o.y = fmaxf(o.y, 0.f);
                    o.z = fmaxf(o.z, 0.f); o.w = fmaxf(o.w, 0.f);
                }
                *(float4*)(obase + rr * ED + cq * 4) = o;
            }
        }
    }
}

extern "C" void kernel_launch(void* const* d_in, const int* in_sizes, int n_in,
                              void* d_out, int out_size) {
    const float* x     = (const float*)d_in[0];
    const void*  ei    = d_in[1];
    const float* ea    = (const float*)d_in[2];
    const float* inW   = (const float*)d_in[3];
    const float* inb   = (const float*)d_in[4];
    const float* edgeW = (const float*)d_in[5];
    const float* edgeb = (const float*)d_in[6];
    const float* W1    = (const float*)d_in[7];
    const float* b1    = (const float*)d_in[8];
    const float* gamma = (const float*)d_in[9];
    const float* beta  = (const float*)d_in[10];
    const float* W2    = (const float*)d_in[11];
    const float* b2    = (const float*)d_in[12];
    float* out = (float*)d_out;

    void *ph0, *ph1;
    cudaGetSymbolAddress(&ph0, g_h0);
    cudaGetSymbolAddress(&ph1, g_h1);

    cudaFuncSetAttribute(k_gemm1, cudaFuncAttributeMaxDynamicSharedMemorySize, G1_SMEMF * 4);
    cudaFuncSetAttribute(k_gemm2, cudaFuncAttributeMaxDynamicSharedMemorySize, G2_SMEMF * 4);

    k_zero<<<256, 256>>>();                                     // launch 0
    k_detect<<<1, 256>>>((const unsigned int*)ei);              // 1
    k_prep<<<PLACE_BLOCKS, 256>>>(ei, ea);                      // 2
    k_offuv<<<OFF_BLOCKS + NL, 256>>>(edgeW, edgeb, W1);        // 3
    k_place<<<PLACE_BLOCKS + EMB_BLOCKS, 256>>>(x, inW, inb);   // 4

    const float* hin = (const float*)ph0;
    dim3 gGemm((NN + 63) / 64, BB);
    for (int l = 0; l < NL; l++) {
        k_gemm1<<<gGemm, 256, G1_SMEMF * 4>>>(W1 + l * H2 * H2, b1 + l * H2, hin, l); // 5 at l=0
        float* hout = (l == NL - 1) ? out : ((l == 0) ? (float*)ph1 : (float*)ph0);
        k_gemm2<<<gGemm, 256, G2_SMEMF * 4>>>(W2 + l * H2 * ED, b2 + l * ED,
                                              gamma + l * H2, beta + l * H2,
                                              hout, l, (l < NL - 1) ? 1 : 0);
        hin = hout;
    }
}

// round 7
// speedup vs baseline: 1.3787x; 1.1313x over previous
#include <cuda_runtime.h>

#define BB 4
#define NN 20000
#define EE 320000
#define IND 21
#define ED 64
#define H2 128
#define NL 3
#define BN_EPS 1e-5f

#define HSZ  (BB*NN*ED)
#define H2SZ (BB*NN*H2)

// packed fp32x2 helpers (FFMA2 path — bit-exact dual fp32 FMA)
#define FMA2(acc, a, b) \
    asm("fma.rn.f32x2 %0, %1, %2, %0;" : "+l"(acc) : "l"(a), "l"(b))
#define PK2(out, x) \
    asm("mov.b64 %0, {%1, %1};" : "=l"(out) : "r"(__float_as_uint(x)))
#define UNPK(lo, hi, v) \
    { unsigned int _l, _h; asm("mov.b64 {%0, %1}, %2;" : "=r"(_l), "=r"(_h) : "l"(v)); \
      lo = __uint_as_float(_l); hi = __uint_as_float(_h); }

// ---- zero-initialized-per-launch scratch (cleared by k_init) ----
struct ZBuf {
    float sc[2*BB*NN];     // interleaved {attr-sum, deg} per node
    int   fill[BB*NN];
    int   ctr[BB];
    float sum[NL*BB*H2];
    float sumsq[NL*BB*H2];
};
__device__ ZBuf gz;

__device__ int   g_src[BB*EE];
__device__ int   g_dst[BB*EE];
__device__ int   g_off[BB*NN];
__device__ int   g_csr[BB*EE];
__device__ float g_h0[HSZ];
__device__ float g_h1[HSZ];
__device__ float g_h2[H2SZ];
__device__ float g_u[NL*H2];
__device__ float g_v[NL*H2];
__device__ int   g_is64;

// ---- launch 0: zero scratch + dtype detect (block 0) fused ----
__global__ void k_init(const unsigned int* __restrict__ ei32) {
    if (blockIdx.x == 0) {
        __shared__ unsigned int sOr[256];
        sOr[threadIdx.x] = ei32[2 * threadIdx.x + 1];
        __syncthreads();
        for (int s = 128; s > 0; s >>= 1) {
            if (threadIdx.x < s) sOr[threadIdx.x] |= sOr[threadIdx.x + s];
            __syncthreads();
        }
        if (threadIdx.x == 0) g_is64 = (sOr[0] == 0) ? 1 : 0;
    } else {
        int* p = (int*)&gz;
        int n = sizeof(ZBuf) / 4;
        for (int i = (blockIdx.x - 1) * 256 + threadIdx.x; i < n; i += (gridDim.x - 1) * 256)
            p[i] = 0;
    }
}

// ---- launch 1: decode indices + per-node {attr-sum, deg} via one v2 reduction ----
__global__ void __launch_bounds__(256) k_prep(const void* __restrict__ ei,
                                              const float* __restrict__ ea) {
    int idx = blockIdx.x * 256 + threadIdx.x;
    int b = idx / EE;
    int e = idx - b * EE;
    int src, dst;
    if (g_is64) {
        const long long* p = (const long long*)ei + (long long)b * 2 * EE;
        src = (int)p[e];
        dst = (int)p[EE + e];
    } else {
        const int* p = (const int*)ei + (long long)b * 2 * EE;
        src = p[e];
        dst = p[EE + e];
    }
    g_src[idx] = src;
    g_dst[idx] = dst;
    float* p2 = &gz.sc[2 * (b * NN + dst)];
    float a = ea[idx];
    asm volatile("red.global.add.v2.f32 [%0], {%1,%2};"
                 :: "l"(p2), "f"(a), "f"(1.0f) : "memory");
}

// ---- launch 2: CSR offsets (warp-aggregated atomic partition) + rank-2 uv fold ----
#define OFF_BLOCKS ((BB*NN + 255) / 256)   // 313
__global__ void __launch_bounds__(256) k_offuv(const float* __restrict__ edgeW,
                                               const float* __restrict__ edgeb,
                                               const float* __restrict__ W1) {
    if (blockIdx.x < OFF_BLOCKS) {
        int i = blockIdx.x * 256 + threadIdx.x;
        if (i < BB * NN) {               // full warps only: 32 | 80000, 32 | 20000
            int b = i / NN;              // uniform within a warp
            int c = (int)gz.sc[2 * i + 1];
            int lane = threadIdx.x & 31;
            int pref = c;
#pragma unroll
            for (int d = 1; d < 32; d <<= 1) {
                int t = __shfl_up_sync(0xFFFFFFFFu, pref, d);
                if (lane >= d) pref += t;
            }
            int total = __shfl_sync(0xFFFFFFFFu, pref, 31);
            int base = 0;
            if (lane == 31) base = atomicAdd(&gz.ctr[b], total);
            base = __shfl_sync(0xFFFFFFFFu, base, 31);
            g_off[i] = b * EE + base + pref - c;
        }
    } else {
        int l = blockIdx.x - OFF_BLOCKS;           // 0..NL-1
        __shared__ float su[2][128], sv[2][128];
        int j = threadIdx.x & 127, hf = threadIdx.x >> 7;
        const float* Wl = W1 + l * H2 * H2;
        float u = 0.f, v = 0.f;
#pragma unroll 8
        for (int c = hf * 32; c < hf * 32 + 32; c++) {
            float wv = Wl[(ED + c) * H2 + j];
            u += edgeW[l * ED + c] * wv;
            v += edgeb[l * ED + c] * wv;
        }
        su[hf][j] = u; sv[hf][j] = v;
        __syncthreads();
        if (hf == 0) {
            g_u[l * H2 + j] = su[0][j] + su[1][j];
            g_v[l * H2 + j] = sv[0][j] + sv[1][j];
        }
    }
}

// ---- launch 3: CSR placement + input embedding (fused, disjoint block ranges) ----
#define PLACE_BLOCKS (BB*EE / 256)   // 5000
#define EMB_BLOCKS   (BB*NN / 64)    // 1250
__global__ void __launch_bounds__(256) k_place(const float* __restrict__ x,
                                               const float* __restrict__ inW,
                                               const float* __restrict__ inb) {
    if (blockIdx.x < PLACE_BLOCKS) {
        int idx = blockIdx.x * 256 + threadIdx.x;
        int b = idx / EE;
        int dst = g_dst[idx];
        int r = atomicAdd(&gz.fill[b * NN + dst], 1);
        g_csr[g_off[b * NN + dst] + r] = g_src[idx];
    } else {
        __shared__ float sW[IND * ED];
        __shared__ float sX[64 * IND];
        int nid0 = (blockIdx.x - PLACE_BLOCKS) * 64;
        int tid = threadIdx.x;
        for (int i = tid; i < IND * ED; i += 256) sW[i] = inW[i];
        for (int i = tid; i < 64 * IND; i += 256) sX[i] = x[(long long)nid0 * IND + i];
        __syncthreads();
        int j = tid & 63;
        float bj = inb[j];
        for (int loc = tid >> 6; loc < 64; loc += 4) {
            float acc = bj;
#pragma unroll
            for (int i = 0; i < IND; i++) acc += sX[loc * IND + i] * sW[i * ED + j];
            g_h0[(long long)(nid0 + loc) * ED + j] = acc;
        }
    }
}

// ---- GEMM1 (fused gather-aggregate, FFMA2 mainloop):
//      h2 = seg_sum(h[src]) @ W1[0:64,:] + s*u + deg*v + b1 ; fused BN stats ----
#define ST1 66
#define G1_SMEMF (8192 + 64*ST1 + 64 + 64 + 64 + 128*5)
__global__ void __launch_bounds__(256) k_gemm1(const float* __restrict__ W1l,
                                               const float* __restrict__ b1l,
                                               const float* __restrict__ hin,
                                               int l) {
    extern __shared__ float sm[];
    float* sW   = sm;                  // 64 x 128
    float* sInT = sW + 8192;           // 64 k x 66 rows (transposed, 8B-aligned pairs)
    float* sS   = sInT + 64 * ST1;
    int*   sOff = (int*)(sS + 64);
    int*   sCnt = sOff + 64;
    float* sU   = (float*)(sCnt + 64);
    float* sV   = sU + 128;
    float* sB   = sV + 128;
    float* sSum = sB + 128;
    float* sSqs = sSum + 128;

    int tid = threadIdx.x;
    int b = blockIdx.y;
    int row0 = blockIdx.x * 64;
    int nrows = NN - row0; if (nrows > 64) nrows = 64;

    for (int i = tid; i < 2048; i += 256) ((float4*)sW)[i] = ((const float4*)W1l)[i];
    for (int i = tid; i < 128; i += 256) {
        sU[i] = g_u[l * H2 + i]; sV[i] = g_v[l * H2 + i]; sB[i] = b1l[i];
        sSum[i] = 0.f; sSqs[i] = 0.f;
    }
    if (tid < 64) {
        int ok = tid < nrows;
        int i = b * NN + row0 + tid;
        sOff[tid] = ok ? g_off[i] : 0;
        sCnt[tid] = ok ? (int)gz.sc[2 * i + 1] : 0;
        sS[tid]   = ok ? gz.sc[2 * i] : 0.f;
    }
    __syncthreads();

    // gather + segment-sum straight from h; write TRANSPOSED into sInT[k][row]
    {
        int q4 = (tid & 15) * 4;
        int g = tid >> 4;
        const float* hb = hin + (long long)b * NN * ED;
#pragma unroll
        for (int rr = g * 4; rr < g * 4 + 4; rr++) {
            int off = sOff[rr], c = sCnt[rr];
            float ax = 0.f, ay = 0.f, az = 0.f, aw = 0.f;
            for (int e = 0; e < c; e++) {
                int src = g_csr[off + e];
                float4 v = *(const float4*)(hb + (long long)src * ED + q4);
                ax += v.x; ay += v.y; az += v.z; aw += v.w;
            }
            sInT[(q4 + 0) * ST1 + rr] = ax;
            sInT[(q4 + 1) * ST1 + rr] = ay;
            sInT[(q4 + 2) * ST1 + rr] = az;
            sInT[(q4 + 3) * ST1 + rr] = aw;
        }
    }
    __syncthreads();

    int cq = tid & 31, rg = tid >> 5;   // 32 colquads x 8 rowgroups(8 rows)
    unsigned long long acc2[4][4];      // [rowpair][col]
#pragma unroll
    for (int p = 0; p < 4; p++)
        acc2[p][0] = acc2[p][1] = acc2[p][2] = acc2[p][3] = 0ull;

#pragma unroll 8
    for (int k = 0; k < 64; k++) {
        float4 w = *(const float4*)(sW + k * 128 + cq * 4);
        unsigned long long wb0, wb1, wb2, wb3;
        PK2(wb0, w.x); PK2(wb1, w.y); PK2(wb2, w.z); PK2(wb3, w.w);
        const unsigned long long* arow =
            (const unsigned long long*)(sInT + k * ST1 + rg * 8);
#pragma unroll
        for (int p = 0; p < 4; p++) {
            unsigned long long ap = arow[p];
            FMA2(acc2[p][0], ap, wb0);
            FMA2(acc2[p][1], ap, wb1);
            FMA2(acc2[p][2], ap, wb2);
            FMA2(acc2[p][3], ap, wb3);
        }
    }

    float u0 = sU[cq*4], u1 = sU[cq*4+1], u2 = sU[cq*4+2], u3 = sU[cq*4+3];
    float v0 = sV[cq*4], v1 = sV[cq*4+1], v2 = sV[cq*4+2], v3 = sV[cq*4+3];
    float bb0 = sB[cq*4], bb1 = sB[cq*4+1], bb2 = sB[cq*4+2], bb3 = sB[cq*4+3];
    float ps0=0,ps1=0,ps2=0,ps3=0, pq0=0,pq1=0,pq2=0,pq3=0;
    float* obase = g_h2 + ((long long)b * NN + row0) * H2;
#pragma unroll
    for (int p = 0; p < 4; p++) {
        float o_[2][4];
        UNPK(o_[0][0], o_[1][0], acc2[p][0]);
        UNPK(o_[0][1], o_[1][1], acc2[p][1]);
        UNPK(o_[0][2], o_[1][2], acc2[p][2]);
        UNPK(o_[0][3], o_[1][3], acc2[p][3]);
#pragma unroll
        for (int t = 0; t < 2; t++) {
            int rr = rg * 8 + 2 * p + t;
            if (rr < nrows) {
                float s = sS[rr], d = (float)sCnt[rr];
                float o0 = o_[t][0] + s*u0 + d*v0 + bb0;
                float o1 = o_[t][1] + s*u1 + d*v1 + bb1;
                float o2 = o_[t][2] + s*u2 + d*v2 + bb2;
                float o3 = o_[t][3] + s*u3 + d*v3 + bb3;
                float4 o = {o0, o1, o2, o3};
                *(float4*)(obase + rr * H2 + cq * 4) = o;
                ps0 += o0; ps1 += o1; ps2 += o2; ps3 += o3;
                pq0 += o0*o0; pq1 += o1*o1; pq2 += o2*o2; pq3 += o3*o3;
            }
        }
    }
    atomicAdd(sSum + cq*4,     ps0); atomicAdd(sSum + cq*4 + 1, ps1);
    atomicAdd(sSum + cq*4 + 2, ps2); atomicAdd(sSum + cq*4 + 3, ps3);
    atomicAdd(sSqs + cq*4,     pq0); atomicAdd(sSqs + cq*4 + 1, pq1);
    atomicAdd(sSqs + cq*4 + 2, pq2); atomicAdd(sSqs + cq*4 + 3, pq3);
    __syncthreads();
    float* gsum = gz.sum   + l * BB * H2 + b * H2;
    float* gsq  = gz.sumsq + l * BB * H2 + b * H2;
    for (int i = tid; i < 128; i += 256) {
        atomicAdd(&gsum[i], sSum[i]);
        atomicAdd(&gsq[i],  sSqs[i]);
    }
}

// ---- GEMM2 (BN finalize fused, FFMA2 mainloop): out = relu?(relu(BN(h2)) @ W2 + b2) ----
#define ST2 66
#define G2_SMEMF (8192 + 128*ST2 + 256)
__global__ void __launch_bounds__(256) k_gemm2(const float* __restrict__ W2l,
                                               const float* __restrict__ b2l,
                                               const float* __restrict__ gm,
                                               const float* __restrict__ bt,
                                               float* __restrict__ hout,
                                               int l, int relu_out) {
    extern __shared__ float sm[];
    float* sW   = sm;             // 128 x 64
    float* sInT = sW + 8192;      // 128 k x 66 rows (transposed)
    float* sA   = sInT + 128 * ST2;
    float* sC   = sA + 128;
    int tid = threadIdx.x, b = blockIdx.y;
    int row0 = blockIdx.x * 64;
    int nrows = NN - row0; if (nrows > 64) nrows = 64;

    for (int i = tid; i < 2048; i += 256) ((float4*)sW)[i] = ((const float4*)W2l)[i];
    const float* gsum = gz.sum   + l * BB * H2 + b * H2;
    const float* gsq  = gz.sumsq + l * BB * H2 + b * H2;
    for (int i = tid; i < 128; i += 256) {
        float mean = gsum[i] * (1.0f / NN);
        float var  = gsq[i] * (1.0f / NN) - mean * mean;
        float a = gm[i] * rsqrtf(var + BN_EPS);
        sA[i] = a;
        sC[i] = bt[i] - mean * a;
    }
    __syncthreads();

    // stage BN(h2)+relu TRANSPOSED: i -> r = i&63 (warp-consecutive => conflict-free STS)
    const float* ibase = g_h2 + ((long long)b * NN + row0) * H2;
    for (int i = tid; i < 2048; i += 256) {
        int r = i & 63, k4 = i >> 6;   // k4 in 0..31
        float4 v;
        if (r < nrows) {
            v = ((const float4*)ibase)[r * 32 + k4];
            float4 a4 = ((const float4*)sA)[k4];
            float4 c4 = ((const float4*)sC)[k4];
            v.x = fmaxf(v.x * a4.x + c4.x, 0.f);
            v.y = fmaxf(v.y * a4.y + c4.y, 0.f);
            v.z = fmaxf(v.z * a4.z + c4.z, 0.f);
            v.w = fmaxf(v.w * a4.w + c4.w, 0.f);
        } else v = make_float4(0.f, 0.f, 0.f, 0.f);
        sInT[(k4 * 4 + 0) * ST2 + r] = v.x;
        sInT[(k4 * 4 + 1) * ST2 + r] = v.y;
        sInT[(k4 * 4 + 2) * ST2 + r] = v.z;
        sInT[(k4 * 4 + 3) * ST2 + r] = v.w;
    }
    __syncthreads();

    int cq = tid & 15, rg = tid >> 4;   // 16 colquads x 16 rowgroups(4 rows)
    unsigned long long acc2[2][4];
#pragma unroll
    for (int p = 0; p < 2; p++)
        acc2[p][0] = acc2[p][1] = acc2[p][2] = acc2[p][3] = 0ull;

#pragma unroll 8
    for (int k = 0; k < 128; k++) {
        float4 w = *(const float4*)(sW + k * 64 + cq * 4);
        unsigned long long wb0, wb1, wb2, wb3;
        PK2(wb0, w.x); PK2(wb1, w.y); PK2(wb2, w.z); PK2(wb3, w.w);
        const unsigned long long* arow =
            (const unsigned long long*)(sInT + k * ST2 + rg * 4);
#pragma unroll
        for (int p = 0; p < 2; p++) {
            unsigned long long ap = arow[p];
            FMA2(acc2[p][0], ap, wb0);
            FMA2(acc2[p][1], ap, wb1);
            FMA2(acc2[p][2], ap, wb2);
            FMA2(acc2[p][3], ap, wb3);
        }
    }

    float4 bb = ((const float4*)b2l)[cq];
    float* obase = hout + ((long long)b * NN + row0) * ED;
#pragma unroll
    for (int p = 0; p < 2; p++) {
        float o_[2][4];
        UNPK(o_[0][0], o_[1][0], acc2[p][0]);
        UNPK(o_[0][1], o_[1][1], acc2[p][1]);
        UNPK(o_[0][2], o_[1][2], acc2[p][2]);
        UNPK(o_[0][3], o_[1][3], acc2[p][3]);
#pragma unroll
        for (int t = 0; t < 2; t++) {
            int rr = rg * 4 + 2 * p + t;
            if (rr < nrows) {
                float4 o = {o_[t][0] + bb.x, o_[t][1] + bb.y,
                            o_[t][2] + bb.z, o_[t][3] + bb.w};
                if (relu_out) {
                    o.x = fmaxf(o.x, 0.f); o.y = fmaxf(o.y, 0.f);
                    o.z = fmaxf(o.z, 0.f); o.w = fmaxf(o.w, 0.f);
                }
                *(float4*)(obase + rr * ED + cq * 4) = o;
            }
        }
    }
}

extern "C" void kernel_launch(void* const* d_in, const int* in_sizes, int n_in,
                              void* d_out, int out_size) {
    const float* x     = (const float*)d_in[0];
    const void*  ei    = d_in[1];
    const float* ea    = (const float*)d_in[2];
    const float* inW   = (const float*)d_in[3];
    const float* inb   = (const float*)d_in[4];
    const float* edgeW = (const float*)d_in[5];
    const float* edgeb = (const float*)d_in[6];
    const float* W1    = (const float*)d_in[7];
    const float* b1    = (const float*)d_in[8];
    const float* gamma = (const float*)d_in[9];
    const float* beta  = (const float*)d_in[10];
    const float* W2    = (const float*)d_in[11];
    const float* b2    = (const float*)d_in[12];
    float* out = (float*)d_out;

    void *ph0, *ph1;
    cudaGetSymbolAddress(&ph0, g_h0);
    cudaGetSymbolAddress(&ph1, g_h1);

    cudaFuncSetAttribute(k_gemm1, cudaFuncAttributeMaxDynamicSharedMemorySize, G1_SMEMF * 4);
    cudaFuncSetAttribute(k_gemm2, cudaFuncAttributeMaxDynamicSharedMemorySize, G2_SMEMF * 4);

    k_init<<<257, 256>>>((const unsigned int*)ei);              // 0
    k_prep<<<PLACE_BLOCKS, 256>>>(ei, ea);                      // 1
    k_offuv<<<OFF_BLOCKS + NL, 256>>>(edgeW, edgeb, W1);        // 2
    k_place<<<PLACE_BLOCKS + EMB_BLOCKS, 256>>>(x, inW, inb);   // 3

    const float* hin = (const float*)ph0;
    dim3 gGemm((NN + 63) / 64, BB);
    for (int l = 0; l < NL; l++) {
        k_gemm1<<<gGemm, 256, G1_SMEMF * 4>>>(W1 + l * H2 * H2, b1 + l * H2, hin, l); // 4 at l=0
        float* hout = (l == NL - 1) ? out : ((l == 0) ? (float*)ph1 : (float*)ph0);
        k_gemm2<<<gGemm, 256, G2_SMEMF * 4>>>(W2 + l * H2 * ED, b2 + l * ED,          // 5 at l=0
                                              gamma + l * H2, beta + l * H2,
                                              hout, l, (l < NL - 1) ? 1 : 0);
        hin = hout;
    }
}